// round 4
// baseline (speedup 1.0000x reference)
#include <cuda_runtime.h>

#define NB    8
#define NA    3
#define NH    160
#define NW    160
#define NCLS  80
#define NG    32
#define NPB   (NA*NH*NW)        // 76800 cells per batch
#define NCELL (NB*NPB)          // 614400 total cells
#define BLOCKS_PER_BATCH (NPB/256)  // 300

__device__ float4 d_gtc[NB*NG];     // precomputed gt corners (x1,y1,x2,y2), degenerate if masked
__device__ float  d_garea[NB*NG];   // gt area (0 if masked)
__device__ float  d_maskf[NB*NG];   // mask as float
__device__ int    d_hasgt[NB];
__device__ double d_loss[4];        // xy, wh, cls, conf

__constant__ float c_anch[9][2] = {
    {10.f,13.f},{16.f,30.f},{33.f,23.f},{30.f,61.f},{62.f,45.f},
    {59.f,119.f},{116.f,90.f},{156.f,198.f},{373.f,326.f}};

__device__ __forceinline__ float sigmoidf_(float x){
    return __fdividef(1.0f, 1.0f + __expf(-x));
}
__device__ __forceinline__ float bcef_(float x, float t){
    // max(x,0) - x*t + log(1 + exp(-|x|))
    return fmaxf(x, 0.0f) - x*t + __logf(1.0f + __expf(-fabsf(x)));
}

// ---------------------------------------------------------------------------
// Kernel 0: decode gt_mask (dtype-agnostic), precompute gt corners/areas,
// per-batch has_gt, zero loss accumulators. 1 block x 256 threads.
// ---------------------------------------------------------------------------
__global__ void prep_kernel(const float* __restrict__ gtb, const void* __restrict__ gmask)
{
    int t = threadIdx.x;            // 0..255, t = b*32 + g
    __shared__ int sNon01, sOff4;
    if (t == 0){ sNon01 = 0; sOff4 = 0; }
    __syncthreads();

    const unsigned char* by = (const unsigned char*)gmask;
    unsigned char v = by[t];                       // first 256 bytes safe for any dtype
    if (v > 1)            atomicOr(&sNon01, 1);    // not a 0/1 byte -> 4-byte elements
    if ((t & 3) && v)     atomicOr(&sOff4, 1);     // nonzero off 4-byte boundary -> bool bytes
    __syncthreads();

    bool isBool = (!sNon01) && sOff4;
    bool m;
    if (isBool) m = (by[t] != 0);
    else        m = (((const unsigned int*)gmask)[t] != 0u);  // int32 or float32: word!=0

    float4 g = ((const float4*)gtb)[t];
    float cx = g.x, cy = g.y, w = g.z, h = g.w;
    float4 c; float area;
    if (m){
        c.x = cx - 0.5f*w; c.y = cy - 0.5f*h;
        c.z = cx + 0.5f*w; c.w = cy + 0.5f*h;
        area = w*h;
    } else {
        c = make_float4(0.f,0.f,0.f,0.f); area = 0.f;
    }
    d_gtc[t]   = c;
    d_garea[t] = area;
    d_maskf[t] = m ? 1.f : 0.f;

    unsigned ball = __ballot_sync(0xFFFFFFFFu, m);
    if ((t & 31) == 0) d_hasgt[t >> 5] = (ball != 0u);
    if (t < 4) d_loss[t] = 0.0;
}

// ---------------------------------------------------------------------------
// Kernel 1 (heavy, HBM-bound): thread-per-cell.
// p_bbox, cls argmax/score, tconf via 32 IoUs, conf BCE -> block-reduced atomic.
// ---------------------------------------------------------------------------
__global__ __launch_bounds__(256) void main_kernel(
    const float* __restrict__ t_bbox, const float* __restrict__ conf,
    const float* __restrict__ cls,    float* __restrict__ out)
{
    __shared__ float4 s_gtc[NG];
    __shared__ float  s_area[NG];
    __shared__ float  s_warp[8];

    int b   = blockIdx.x / BLOCKS_PER_BATCH;
    int tid = threadIdx.x;
    if (tid < NG){
        s_gtc[tid]  = d_gtc[b*NG + tid];
        s_area[tid] = d_garea[b*NG + tid];
    }
    __syncthreads();

    int cell = blockIdx.x*256 + tid;
    int n = cell - b*NPB;
    int a = n / (NH*NW);
    int r = n - a*(NH*NW);
    int j = r / NW;
    int i = r - j*NW;

    // ---- class argmax over 80 logits (float4 loads, coalesced across threads) ----
    const float4* cp = (const float4*)(cls + (size_t)cell*NCLS);
    float m = -__int_as_float(0x7f800000);  // -inf
    int   mi = 0;
    #pragma unroll
    for (int q = 0; q < NCLS/4; q++){
        float4 v = cp[q];
        int c0 = q*4;
        if (v.x > m){ m = v.x; mi = c0;   }
        if (v.y > m){ m = v.y; mi = c0+1; }
        if (v.z > m){ m = v.z; mi = c0+2; }
        if (v.w > m){ m = v.w; mi = c0+3; }
    }

    // ---- decode p_bbox ----
    float4 tb = ((const float4*)t_bbox)[cell];
    float sx = sigmoidf_(tb.x), sy = sigmoidf_(tb.y);
    float sw = sigmoidf_(tb.z), sh = sigmoidf_(tb.w);
    float px = (sx*2.f - 0.5f + (float)i)*8.0f;
    float py = (sy*2.f - 0.5f + (float)j)*8.0f;
    float tw = sw*2.f, th = sh*2.f;
    float pw = tw*tw*c_anch[a][0];
    float ph = th*th*c_anch[a][1];

    float cl = conf[cell];
    float score = sigmoidf_(cl) * sigmoidf_(m);

    // ---- outputs: p_bbox | cls_idx | score ----
    ((float4*)out)[cell]     = make_float4(px, py, pw, ph);
    out[NCELL*4 + cell]      = (float)mi;
    out[NCELL*5 + cell]      = score;

    // ---- tconf = max IoU over 32 gts (masked gts are degenerate -> iou 0) ----
    float px1 = px - 0.5f*pw, px2 = px + 0.5f*pw;
    float py1 = py - 0.5f*ph, py2 = py + 0.5f*ph;
    float parea = pw*ph;
    float best = 0.f;
    #pragma unroll 8
    for (int g = 0; g < NG; g++){
        float4 gc = s_gtc[g];                        // broadcast LDS
        float iw = fminf(px2, gc.z) - fmaxf(px1, gc.x);
        float ih = fminf(py2, gc.w) - fmaxf(py1, gc.y);
        iw = fmaxf(iw, 0.f); ih = fmaxf(ih, 0.f);
        float inter = iw*ih;
        float uni   = parea + s_area[g] - inter;
        float iou   = __fdividef(inter, uni + 1e-16f);
        best = fmaxf(best, iou);
    }
    float tconf = d_hasgt[b] ? best : 0.f;
    float lc = bcef_(cl, tconf);

    // ---- block-reduce loss_conf, one double atomic per block ----
    #pragma unroll
    for (int o = 16; o > 0; o >>= 1) lc += __shfl_down_sync(0xFFFFFFFFu, lc, o);
    if ((tid & 31) == 0) s_warp[tid >> 5] = lc;
    __syncthreads();
    if (tid == 0){
        float s = 0.f;
        #pragma unroll
        for (int w = 0; w < 8; w++) s += s_warp[w];
        atomicAdd(&d_loss[3], (double)s);
    }
}

// ---------------------------------------------------------------------------
// Kernel 2 (tiny): warp per gt (256 warps). Anchor match, gathers, xy/wh/cls BCE.
// ---------------------------------------------------------------------------
__global__ __launch_bounds__(256) void target_kernel(
    const float* __restrict__ t_bbox, const float* __restrict__ cls,
    const float* __restrict__ gtb,    const int* __restrict__ gcls)
{
    int warp = (blockIdx.x*blockDim.x + threadIdx.x) >> 5;
    int lane = threadIdx.x & 31;
    if (warp >= NB*NG) return;
    int b = warp >> 5;

    float mk = d_maskf[warp];
    const float* gp = gtb + warp*4;
    float cx = gp[0], cy = gp[1], gw = gp[2], gh = gp[3];

    // anchor match over all 9 anchors (wh IoU), first-max tiebreak
    float garea = gw*gh;
    float bm = -1.f; int bi = 0;
    #pragma unroll
    for (int k = 0; k < 9; k++){
        float aw = c_anch[k][0], ah = c_anch[k][1];
        float inter = fminf(gw, aw)*fminf(gh, ah);
        float uni   = garea + aw*ah - inter;
        float rr    = inter / (uni + 1e-16f);
        if (rr > bm){ bm = rr; bi = k; }
    }
    bool valid = (mk != 0.f) && (bi < 3);
    if (!valid) return;

    int ta = bi;  // bi < 3 here, so bi % 3 == bi
    float ux = cx*0.125f, uy = cy*0.125f;
    int ti = min(max((int)ux, 0), NW-1);
    int tj = min(max((int)uy, 0), NH-1);
    size_t base = ((((size_t)b*NA + ta)*NH + tj)*NW + ti);
    const float* tbp = t_bbox + base*4;
    const float* clp = cls    + base*NCLS;

    float tgx = (ux - floorf(ux) + 0.5f)*0.5f;
    float tgy = (uy - floorf(uy) + 0.5f)*0.5f;
    float tgw = sqrtf(gw / c_anch[ta][0])*0.5f;
    float tgh = sqrtf(gh / c_anch[ta][1])*0.5f;

    int gc = gcls[warp];
    float cs = 0.f;
    for (int c = lane; c < NCLS; c += 32)
        cs += bcef_(clp[c], (c == gc) ? 1.f : 0.f);
    #pragma unroll
    for (int o = 16; o > 0; o >>= 1) cs += __shfl_down_sync(0xFFFFFFFFu, cs, o);

    if (lane == 0){
        float lxy = bcef_(tbp[0], tgx) + bcef_(tbp[1], tgy);
        float lwh = bcef_(tbp[2], tgw) + bcef_(tbp[3], tgh);
        atomicAdd(&d_loss[0], (double)lxy);
        atomicAdd(&d_loss[1], (double)lwh);
        atomicAdd(&d_loss[2], (double)(cs * (1.f/NCLS)));
    }
}

// ---------------------------------------------------------------------------
// Kernel 3: finalize scalar loss
// ---------------------------------------------------------------------------
__global__ void fin_kernel(float* __restrict__ out)
{
    out[NCELL*6] = (float)((d_loss[0] + d_loss[1] + d_loss[2] + d_loss[3]) * (1.0/NB));
}

extern "C" void kernel_launch(void* const* d_in, const int* in_sizes, int n_in,
                              void* d_out, int out_size)
{
    const float* t_bbox = (const float*)d_in[0];
    const float* conf   = (const float*)d_in[1];
    const float* cls    = (const float*)d_in[2];
    const float* gtb    = (const float*)d_in[3];
    const int*   gcls   = (const int*)  d_in[4];
    const void*  gmask  =               d_in[5];
    float* out = (float*)d_out;

    prep_kernel<<<1, 256>>>(gtb, gmask);
    main_kernel<<<NCELL/256, 256>>>(t_bbox, conf, cls, out);
    target_kernel<<<32, 256>>>(t_bbox, cls, gtb, gcls);
    fin_kernel<<<1, 1>>>(out);
}